// round 15
// baseline (speedup 1.0000x reference)
#include <cuda_runtime.h>

// Fused filtered-lrelu: coalesced x staging (float2, 8B-aligned) -> up-H from
// smem (no predicates) -> per-column up-V + lrelu + down-V (f32x2 phase-packed)
// -> down-H. x: [1024,130,130] f32 -> out: [1024,128,128] f32.

#define IH 130
#define IW 130
#define OW 128
#define XP 44      // Xs stride (42 rows x 44 cols incl pad)
#define TP 80      // t stride (42 rows x 74 cols), mult of 4 for STS.128
#define WP 76      // w stride (32 rows x 74 cols), mult of 4
#define NTHREADS 256

// scalar up-pair (stage A): 6 unique symmetric taps g0..g5
#define UP_E(w0,w1,w2,w3,w4,w5) \
    fmaf(g0,(w5), fmaf(g2,(w4), fmaf(g4,(w3), fmaf(g5,(w2), fmaf(g3,(w1), g1*(w0))))))
#define UP_O(w0,w1,w2,w3,w4,w5) \
    fmaf(g1,(w5), fmaf(g3,(w4), fmaf(g5,(w3), fmaf(g4,(w2), fmaf(g2,(w1), g0*(w0))))))
// 12-tap symmetric down filter over v0..v11:
#define DN(v0,v1,v2,v3,v4,v5,v6,v7,v8,v9,v10,v11) \
    fmaf(e0,(v11), fmaf(e1,(v10), fmaf(e2,(v9), fmaf(e3,(v8), fmaf(e4,(v7), \
    fmaf(e5,(v6),  fmaf(e5,(v5),  fmaf(e4,(v4), fmaf(e3,(v3), fmaf(e2,(v2), \
    fmaf(e1,(v1),  e0*(v0))))))))))))

__device__ __forceinline__ float2 ffma2(float2 a, float2 b, float2 c) {
    float2 d;
    asm("{\n\t.reg .b64 A,B,C,D;\n\t"
        "mov.b64 A,{%2,%3};\n\tmov.b64 B,{%4,%5};\n\tmov.b64 C,{%6,%7};\n\t"
        "fma.rn.f32x2 D,A,B,C;\n\t"
        "mov.b64 {%0,%1},D;\n\t}"
        : "=f"(d.x), "=f"(d.y)
        : "f"(a.x), "f"(a.y), "f"(b.x), "f"(b.y), "f"(c.x), "f"(c.y));
    return d;
}
__device__ __forceinline__ float2 fmul2(float2 a, float2 b) {
    float2 d;
    asm("{\n\t.reg .b64 A,B,D;\n\t"
        "mov.b64 A,{%2,%3};\n\tmov.b64 B,{%4,%5};\n\t"
        "mul.rn.f32x2 D,A,B;\n\t"
        "mov.b64 {%0,%1},D;\n\t}"
        : "=f"(d.x), "=f"(d.y)
        : "f"(a.x), "f"(a.y), "f"(b.x), "f"(b.y));
    return d;
}

__global__ __launch_bounds__(NTHREADS)
void flrelu_fused_kernel(const float* __restrict__ x,
                         const float* __restrict__ fup,
                         const float* __restrict__ fdn,
                         float* __restrict__ out)
{
    __shared__ __align__(16) float t[42 * TP];   // 13.4 KB
    __shared__ __align__(16) float S2[32 * WP];  //  9.7 KB (2432 floats)
    float* Xs = S2;                              // 42*44 = 1848 floats (stage 0/A)
    float* w  = S2;                              // 32*76 (stage B/C), barrier-separated

    const float g0 = fup[0] * 2.0f, g1 = fup[1] * 2.0f, g2 = fup[2] * 2.0f,
                g3 = fup[3] * 2.0f, g4 = fup[4] * 2.0f, g5 = fup[5] * 2.0f;
    const float e0 = fdn[0], e1 = fdn[1], e2 = fdn[2],
                e3 = fdn[3], e4 = fdn[4], e5 = fdn[5];

    const int tile = blockIdx.x;
    const int ch   = blockIdx.y;
    const int m0   = (tile >> 2) * 32;
    const int n0   = (tile & 3) * 32;
    const int tid  = threadIdx.x;

    // ---- Stage 0: coalesced float2 staging of x tile [42 x 44] (zero-padded).
    // 42 rows x 22 float2 units = 924. gc = n0-4+2*c2 is even, and gr*IW is
    // even, so the gmem float2 address is always 8B-aligned. Pair in-bounds
    // iff 0 <= gc <= 128 (gc==128 covers cols {128,129}).
    {
        const float* xc = x + (size_t)ch * IH * IW;
#pragma unroll
        for (int u = 0; u < 4; u++) {
            int idx = tid + u * NTHREADS;
            if (idx < 924) {
                int r  = idx / 22;
                int c2 = idx - 22 * r;
                int lc = 2 * c2;
                int gr = m0 - 4 + r;
                int gc = n0 - 4 + lc;
                float2 v = make_float2(0.f, 0.f);
                if ((unsigned)gr < (unsigned)IH && (unsigned)gc <= 128u)
                    v = *reinterpret_cast<const float2*>(xc + (size_t)gr * IW + gc);
                *reinterpret_cast<float2*>(&Xs[r * XP + lc]) = v;
            }
        }
    }
    __syncthreads();

    // ---- Stage A: horizontal 2x-up from smem, unpredicated LDS.64 windows.
    if (tid < 252) {
        const int r = tid / 6, s = tid - 6 * (tid / 6);
        const float* xr = &Xs[r * XP + 6 * s];
        float xa[14];
#pragma unroll
        for (int p = 0; p < 7; p++) {
            float2 v = *reinterpret_cast<const float2*>(xr + 2 * p);
            xa[2 * p] = v.x; xa[2 * p + 1] = v.y;
        }
        float2 o[7];
#pragma unroll
        for (int k = 0; k < 7; k++) {
            o[k] = make_float2(UP_E(xa[k],xa[k+1],xa[k+2],xa[k+3],xa[k+4],xa[k+5]),
                               UP_O(xa[k],xa[k+1],xa[k+2],xa[k+3],xa[k+4],xa[k+5]));
        }
        float* trow = t + r * TP + 12 * s;
        *reinterpret_cast<float4*>(trow)      = make_float4(o[0].x,o[0].y,o[1].x,o[1].y);
        *reinterpret_cast<float4*>(trow + 4)  = make_float4(o[2].x,o[2].y,o[3].x,o[3].y);
        *reinterpret_cast<float4*>(trow + 8)  = make_float4(o[4].x,o[4].y,o[5].x,o[5].y);
        *reinterpret_cast<float2*>(trow + 12) = o[6];
    }
    __syncthreads();

    // ---- Stage B: per-column up-V + lrelu + down-V, f32x2 over (ze,zo).
    // 74 cols x 2 row-segments (16 outputs each). Sliding dup-packed window.
    // Guards: acc_i update at step k useful iff 5 <= k+i <= 20 (compile-time).
    if (tid < 148) {
        const int seg = (tid >= 74) ? 1 : 0;
        const int j   = tid - 74 * seg;
        const int mb  = seg << 4;                  // 0 or 16
        const float* tc = t + mb * TP + j;
        const float2 P0 = make_float2(g1, g0), P1 = make_float2(g3, g2),
                     P2 = make_float2(g5, g4), P3 = make_float2(g4, g5),
                     P4 = make_float2(g2, g3), P5 = make_float2(g0, g1);
        const float2 ED0 = make_float2(e1, e0), ED1 = make_float2(e3, e2),
                     ED2 = make_float2(e5, e4), ED3 = make_float2(e4, e5),
                     ED4 = make_float2(e2, e3), ED5 = make_float2(e0, e1);
        float2 wb[6];
#pragma unroll
        for (int i = 0; i < 6; i++) {
            float v = tc[i * TP];
            wb[i] = make_float2(v, v);
        }
        float2 acc0 = make_float2(0.f, 0.f), acc1 = acc0, acc2 = acc0,
               acc3 = acc0, acc4 = acc0;
        float* wc = w + j;
#pragma unroll
        for (int k = 0; k < 21; k++) {
            float2 zz = fmul2(P0, wb[k % 6]);
            zz = ffma2(P1, wb[(k + 1) % 6], zz);
            zz = ffma2(P2, wb[(k + 2) % 6], zz);
            zz = ffma2(P3, wb[(k + 3) % 6], zz);
            zz = ffma2(P4, wb[(k + 4) % 6], zz);
            zz = ffma2(P5, wb[(k + 5) % 6], zz);
            zz.x = fmaxf(zz.x, 0.01f * zz.x);      // lrelu on both phases
            zz.y = fmaxf(zz.y, 0.01f * zz.y);
            if (k >= 5)            acc0 = ffma2(ED0, zz, acc0);
            if (k >= 4 && k <= 19) acc1 = ffma2(ED1, zz, acc1);
            if (k >= 3 && k <= 18) acc2 = ffma2(ED2, zz, acc2);
            if (k >= 2 && k <= 17) acc3 = ffma2(ED3, zz, acc3);
            if (k >= 1 && k <= 16) acc4 = ffma2(ED4, zz, acc4);
            if (k >= 5) wc[(mb + k - 5) * WP] = acc0.x + acc0.y;
            acc0 = acc1; acc1 = acc2; acc2 = acc3; acc3 = acc4;
            if (k <= 15) acc4 = fmul2(ED5, zz);    // fresh tail accumulator
            if (k <= 19) {                         // slide: load row k+6
                float v = tc[(k + 6) * TP];
                wb[k % 6] = make_float2(v, v);
            }
        }
    }
    __syncthreads();

    // ---- Stage C: horizontal down + store.
    {
        const int m = tid >> 3, s = tid & 7;
        const float4* wr = reinterpret_cast<const float4*>(w + m * WP) + 2 * s;
        float4 q0 = wr[0], q1 = wr[1], q2 = wr[2], q3 = wr[3], q4 = wr[4];
        float v0=q0.x,v1=q0.y,v2=q0.z,v3=q0.w,
              v4=q1.x,v5=q1.y,v6=q1.z,v7=q1.w,
              v8=q2.x,v9=q2.y,v10=q2.z,v11=q2.w,
              v12=q3.x,v13=q3.y,v14=q3.z,v15=q3.w,
              v16=q4.x,v17=q4.y;
        float o0 = DN(v0,v1,v2,v3,v4,v5,v6,v7,v8,v9,v10,v11);
        float o1 = DN(v2,v3,v4,v5,v6,v7,v8,v9,v10,v11,v12,v13);
        float o2 = DN(v4,v5,v6,v7,v8,v9,v10,v11,v12,v13,v14,v15);
        float o3 = DN(v6,v7,v8,v9,v10,v11,v12,v13,v14,v15,v16,v17);
        float* od = out + (size_t)ch * OW * OW + (size_t)(m0 + m) * OW + n0 + 4 * s;
        *reinterpret_cast<float4*>(od) = make_float4(o0, o1, o2, o3);
    }
}

extern "C" void kernel_launch(void* const* d_in, const int* in_sizes, int n_in,
                              void* d_out, int out_size) {
    const float* x   = (const float*)d_in[0];
    const float* fup = (const float*)d_in[1];
    const float* fdn = (const float*)d_in[2];
    float* out = (float*)d_out;
    dim3 grid(16, 1024);
    flrelu_fused_kernel<<<grid, NTHREADS>>>(x, fup, fdn, out);
}

// round 16
// speedup vs baseline: 1.0215x; 1.0215x over previous
#include <cuda_runtime.h>

// Fused filtered-lrelu, 64x32 output tile: up-H from gmem (LDG.64) ->
// per-column up-V + lrelu + down-V (f32x2 phase-packed, z in registers) ->
// down-H. x: [1024,130,130] f32 -> out: [1024,128,128] f32.

#define IH 130
#define IW 130
#define OW 128
#define TP 80      // t stride (74 rows x 74 cols), mult of 4 for STS.128
#define WP 76      // w stride (64 rows x 74 cols), mult of 4
#define NTHREADS 256

// scalar up-pair (stage A): 6 unique symmetric taps g0..g5
#define UP_E(w0,w1,w2,w3,w4,w5) \
    fmaf(g0,(w5), fmaf(g2,(w4), fmaf(g4,(w3), fmaf(g5,(w2), fmaf(g3,(w1), g1*(w0))))))
#define UP_O(w0,w1,w2,w3,w4,w5) \
    fmaf(g1,(w5), fmaf(g3,(w4), fmaf(g5,(w3), fmaf(g4,(w2), fmaf(g2,(w1), g0*(w0))))))
// 12-tap symmetric down filter over v0..v11:
#define DN(v0,v1,v2,v3,v4,v5,v6,v7,v8,v9,v10,v11) \
    fmaf(e0,(v11), fmaf(e1,(v10), fmaf(e2,(v9), fmaf(e3,(v8), fmaf(e4,(v7), \
    fmaf(e5,(v6),  fmaf(e5,(v5),  fmaf(e4,(v4), fmaf(e3,(v3), fmaf(e2,(v2), \
    fmaf(e1,(v1),  e0*(v0))))))))))))

__device__ __forceinline__ float2 ffma2(float2 a, float2 b, float2 c) {
    float2 d;
    asm("{\n\t.reg .b64 A,B,C,D;\n\t"
        "mov.b64 A,{%2,%3};\n\tmov.b64 B,{%4,%5};\n\tmov.b64 C,{%6,%7};\n\t"
        "fma.rn.f32x2 D,A,B,C;\n\t"
        "mov.b64 {%0,%1},D;\n\t}"
        : "=f"(d.x), "=f"(d.y)
        : "f"(a.x), "f"(a.y), "f"(b.x), "f"(b.y), "f"(c.x), "f"(c.y));
    return d;
}
__device__ __forceinline__ float2 fmul2(float2 a, float2 b) {
    float2 d;
    asm("{\n\t.reg .b64 A,B,D;\n\t"
        "mov.b64 A,{%2,%3};\n\tmov.b64 B,{%4,%5};\n\t"
        "mul.rn.f32x2 D,A,B;\n\t"
        "mov.b64 {%0,%1},D;\n\t}"
        : "=f"(d.x), "=f"(d.y)
        : "f"(a.x), "f"(a.y), "f"(b.x), "f"(b.y));
    return d;
}

__global__ __launch_bounds__(NTHREADS)
void flrelu_fused_kernel(const float* __restrict__ x,
                         const float* __restrict__ fup,
                         const float* __restrict__ fdn,
                         float* __restrict__ out)
{
    __shared__ __align__(16) float t[74 * TP];   // 23.7 KB
    __shared__ __align__(16) float w[64 * WP];   // 19.4 KB

    const float g0 = fup[0] * 2.0f, g1 = fup[1] * 2.0f, g2 = fup[2] * 2.0f,
                g3 = fup[3] * 2.0f, g4 = fup[4] * 2.0f, g5 = fup[5] * 2.0f;
    const float e0 = fdn[0], e1 = fdn[1], e2 = fdn[2],
                e3 = fdn[3], e4 = fdn[4], e5 = fdn[5];

    const int tile = blockIdx.x;              // 0..7 (2 row-tiles x 4 col-tiles)
    const int ch   = blockIdx.y;
    const int m0   = (tile >> 2) * 64;        // 0 or 64
    const int n0   = (tile & 3) * 32;         // 0,32,64,96
    const int tid  = threadIdx.x;

    // ---- Stage A: horizontal 2x-up from gmem with LDG.64 windows.
    // 74 rows x 6 segments = 444 jobs; <=2 jobs/thread. Window start
    // gc0 = n0-4+6s is even; IW even -> each float2 fully in/out of bounds.
    {
        const float* xbase = x + (size_t)ch * IH * IW;
        const bool interior = (n0 == 32 || n0 == 64);
#pragma unroll
        for (int it = 0; it < 2; it++) {
            int idx = tid + it * NTHREADS;
            if (idx < 444) {
                const int r = idx / 6, s = idx - 6 * (idx / 6);
                const int gr  = m0 - 4 + r;
                const int gc0 = n0 - 4 + 6 * s;
                const bool rok = (unsigned)gr < (unsigned)IH;
                const float2* xrow2 = reinterpret_cast<const float2*>(
                    xbase + (size_t)gr * IW + gc0);
                float xa[14];
                if (interior) {
#pragma unroll
                    for (int p = 0; p < 7; p++) {
                        float2 v = rok ? xrow2[p] : make_float2(0.f, 0.f);
                        xa[2 * p] = v.x; xa[2 * p + 1] = v.y;
                    }
                } else {
#pragma unroll
                    for (int p = 0; p < 7; p++) {
                        bool ok = rok && ((unsigned)(gc0 + 2 * p) < (unsigned)IW);
                        float2 v = ok ? xrow2[p] : make_float2(0.f, 0.f);
                        xa[2 * p] = v.x; xa[2 * p + 1] = v.y;
                    }
                }
                float2 o[7];
#pragma unroll
                for (int k = 0; k < 7; k++) {
                    o[k] = make_float2(
                        UP_E(xa[k],xa[k+1],xa[k+2],xa[k+3],xa[k+4],xa[k+5]),
                        UP_O(xa[k],xa[k+1],xa[k+2],xa[k+3],xa[k+4],xa[k+5]));
                }
                float* trow = t + r * TP + 12 * s;
                *reinterpret_cast<float4*>(trow)      = make_float4(o[0].x,o[0].y,o[1].x,o[1].y);
                *reinterpret_cast<float4*>(trow + 4)  = make_float4(o[2].x,o[2].y,o[3].x,o[3].y);
                *reinterpret_cast<float4*>(trow + 8)  = make_float4(o[4].x,o[4].y,o[5].x,o[5].y);
                *reinterpret_cast<float2*>(trow + 12) = o[6];
            }
        }
    }
    __syncthreads();

    // ---- Stage B: per-column up-V + lrelu + down-V, f32x2 over (ze,zo).
    // 74 cols x 2 row-segments (32 outputs each, 37 steps). Sliding
    // dup-packed 6-slot window; acc_i update at step k useful iff
    // 5 <= k+i <= 36 (compile-time guards).
    if (tid < 148) {
        const int seg = (tid >= 74) ? 1 : 0;
        const int j   = tid - 74 * seg;
        const int mb  = seg << 5;                  // 0 or 32
        const float* tc = t + mb * TP + j;
        const float2 P0 = make_float2(g1, g0), P1 = make_float2(g3, g2),
                     P2 = make_float2(g5, g4), P3 = make_float2(g4, g5),
                     P4 = make_float2(g2, g3), P5 = make_float2(g0, g1);
        const float2 ED0 = make_float2(e1, e0), ED1 = make_float2(e3, e2),
                     ED2 = make_float2(e5, e4), ED3 = make_float2(e4, e5),
                     ED4 = make_float2(e2, e3), ED5 = make_float2(e0, e1);
        float2 wb[6];
#pragma unroll
        for (int i = 0; i < 6; i++) {
            float v = tc[i * TP];
            wb[i] = make_float2(v, v);
        }
        float2 acc0 = make_float2(0.f, 0.f), acc1 = acc0, acc2 = acc0,
               acc3 = acc0, acc4 = acc0;
        float* wc = w + j;
#pragma unroll
        for (int k = 0; k < 37; k++) {
            float2 zz = fmul2(P0, wb[k % 6]);
            zz = ffma2(P1, wb[(k + 1) % 6], zz);
            zz = ffma2(P2, wb[(k + 2) % 6], zz);
            zz = ffma2(P3, wb[(k + 3) % 6], zz);
            zz = ffma2(P4, wb[(k + 4) % 6], zz);
            zz = ffma2(P5, wb[(k + 5) % 6], zz);
            zz.x = fmaxf(zz.x, 0.01f * zz.x);      // lrelu on both phases
            zz.y = fmaxf(zz.y, 0.01f * zz.y);
            if (k >= 5)            acc0 = ffma2(ED0, zz, acc0);
            if (k >= 4 && k <= 35) acc1 = ffma2(ED1, zz, acc1);
            if (k >= 3 && k <= 34) acc2 = ffma2(ED2, zz, acc2);
            if (k >= 2 && k <= 33) acc3 = ffma2(ED3, zz, acc3);
            if (k >= 1 && k <= 32) acc4 = ffma2(ED4, zz, acc4);
            if (k >= 5) wc[(mb + k - 5) * WP] = acc0.x + acc0.y;
            acc0 = acc1; acc1 = acc2; acc2 = acc3; acc3 = acc4;
            if (k <= 31) acc4 = fmul2(ED5, zz);    // fresh tail accumulator
            if (k <= 35) {                         // slide: load row k+6
                float v = tc[(k + 6) * TP];
                wb[k % 6] = make_float2(v, v);
            }
        }
    }
    __syncthreads();

    // ---- Stage C: horizontal down + store. 64 rows x 8 segs = 512 jobs,
    // 2 jobs/thread. Job (m, s): out cols 4s..4s+3 of row m from
    // w[m][8s..8s+17] (5 LDS.128), float4 store.
    {
        float* ob = out + (size_t)ch * OW * OW;
#pragma unroll
        for (int it = 0; it < 2; it++) {
            const int job = tid + it * NTHREADS;
            const int m = job >> 3, s = job & 7;
            const float4* wr = reinterpret_cast<const float4*>(w + m * WP) + 2 * s;
            float4 q0 = wr[0], q1 = wr[1], q2 = wr[2], q3 = wr[3], q4 = wr[4];
            float v0=q0.x,v1=q0.y,v2=q0.z,v3=q0.w,
                  v4=q1.x,v5=q1.y,v6=q1.z,v7=q1.w,
                  v8=q2.x,v9=q2.y,v10=q2.z,v11=q2.w,
                  v12=q3.x,v13=q3.y,v14=q3.z,v15=q3.w,
                  v16=q4.x,v17=q4.y;
            float o0 = DN(v0,v1,v2,v3,v4,v5,v6,v7,v8,v9,v10,v11);
            float o1 = DN(v2,v3,v4,v5,v6,v7,v8,v9,v10,v11,v12,v13);
            float o2 = DN(v4,v5,v6,v7,v8,v9,v10,v11,v12,v13,v14,v15);
            float o3 = DN(v6,v7,v8,v9,v10,v11,v12,v13,v14,v15,v16,v17);
            float* od = ob + (size_t)(m0 + m) * OW + n0 + 4 * s;
            *reinterpret_cast<float4*>(od) = make_float4(o0, o1, o2, o3);
        }
    }
}

extern "C" void kernel_launch(void* const* d_in, const int* in_sizes, int n_in,
                              void* d_out, int out_size) {
    const float* x   = (const float*)d_in[0];
    const float* fup = (const float*)d_in[1];
    const float* fdn = (const float*)d_in[2];
    float* out = (float*)d_out;
    dim3 grid(8, 1024);
    flrelu_fused_kernel<<<grid, NTHREADS>>>(x, fup, fdn, out);
}

// round 17
// speedup vs baseline: 1.1828x; 1.1578x over previous
#include <cuda_runtime.h>

// Fused filtered-lrelu, 64x32 tile: up-H from gmem (LDG.64) -> per-column
// up-V + lrelu + down-V (f32x2 phase-packed; seg0 writes results IN PLACE
// into dead t rows, seg1 into a small side buffer) -> down-H.
// x: [1024,130,130] f32 -> out: [1024,128,128] f32, 12-tap symmetric filters.

#define IH 130
#define IW 130
#define OW 128
#define TP 76      // t stride (74 rows x 74 cols), mult of 4 -> 16B-aligned rows
#define NTHREADS 256

// scalar up-pair (stage A): 6 unique symmetric taps g0..g5
#define UP_E(w0,w1,w2,w3,w4,w5) \
    fmaf(g0,(w5), fmaf(g2,(w4), fmaf(g4,(w3), fmaf(g5,(w2), fmaf(g3,(w1), g1*(w0))))))
#define UP_O(w0,w1,w2,w3,w4,w5) \
    fmaf(g1,(w5), fmaf(g3,(w4), fmaf(g5,(w3), fmaf(g4,(w2), fmaf(g2,(w1), g0*(w0))))))
// 12-tap symmetric down filter over v0..v11:
#define DN(v0,v1,v2,v3,v4,v5,v6,v7,v8,v9,v10,v11) \
    fmaf(e0,(v11), fmaf(e1,(v10), fmaf(e2,(v9), fmaf(e3,(v8), fmaf(e4,(v7), \
    fmaf(e5,(v6),  fmaf(e5,(v5),  fmaf(e4,(v4), fmaf(e3,(v3), fmaf(e2,(v2), \
    fmaf(e1,(v1),  e0*(v0))))))))))))

__device__ __forceinline__ float2 ffma2(float2 a, float2 b, float2 c) {
    float2 d;
    asm("{\n\t.reg .b64 A,B,C,D;\n\t"
        "mov.b64 A,{%2,%3};\n\tmov.b64 B,{%4,%5};\n\tmov.b64 C,{%6,%7};\n\t"
        "fma.rn.f32x2 D,A,B,C;\n\t"
        "mov.b64 {%0,%1},D;\n\t}"
        : "=f"(d.x), "=f"(d.y)
        : "f"(a.x), "f"(a.y), "f"(b.x), "f"(b.y), "f"(c.x), "f"(c.y));
    return d;
}
__device__ __forceinline__ float2 fmul2(float2 a, float2 b) {
    float2 d;
    asm("{\n\t.reg .b64 A,B,D;\n\t"
        "mov.b64 A,{%2,%3};\n\tmov.b64 B,{%4,%5};\n\t"
        "mul.rn.f32x2 D,A,B;\n\t"
        "mov.b64 {%0,%1},D;\n\t}"
        : "=f"(d.x), "=f"(d.y)
        : "f"(a.x), "f"(a.y), "f"(b.x), "f"(b.y));
    return d;
}

__global__ __launch_bounds__(NTHREADS, 7)
void flrelu_fused_kernel(const float* __restrict__ x,
                         const float* __restrict__ fup,
                         const float* __restrict__ fdn,
                         float* __restrict__ out)
{
    __shared__ __align__(16) float t[74 * TP];   // 22.5 KB; rows 0..31 become w rows 0..31
    __shared__ __align__(16) float w1[32 * TP];  //  9.5 KB; w rows 32..63

    const float g0 = fup[0] * 2.0f, g1 = fup[1] * 2.0f, g2 = fup[2] * 2.0f,
                g3 = fup[3] * 2.0f, g4 = fup[4] * 2.0f, g5 = fup[5] * 2.0f;
    const float e0 = fdn[0], e1 = fdn[1], e2 = fdn[2],
                e3 = fdn[3], e4 = fdn[4], e5 = fdn[5];

    const int tile = blockIdx.x;              // 0..7 (2 row-tiles x 4 col-tiles)
    const int ch   = blockIdx.y;
    const int m0   = (tile >> 2) * 64;        // 0 or 64
    const int n0   = (tile & 3) * 32;         // 0,32,64,96
    const int tid  = threadIdx.x;

    // ---- Stage A: horizontal 2x-up from gmem with LDG.64 windows.
    // 74 rows x 6 segments = 444 jobs; <=2 per thread (non-unrolled loop to
    // keep register pressure at the single-job level).
    {
        const float* xbase = x + (size_t)ch * IH * IW;
        const bool interior = (n0 == 32 || n0 == 64);
#pragma unroll 1
        for (int idx = tid; idx < 444; idx += NTHREADS) {
            const int r = idx / 6, s = idx - 6 * (idx / 6);
            const int gr  = m0 - 4 + r;
            const int gc0 = n0 - 4 + 6 * s;    // always even; IW even
            const bool rok = (unsigned)gr < (unsigned)IH;
            const float2* xrow2 = reinterpret_cast<const float2*>(
                xbase + (size_t)gr * IW + gc0);
            float xa[14];
            if (interior) {
#pragma unroll
                for (int p = 0; p < 7; p++) {
                    float2 v = rok ? xrow2[p] : make_float2(0.f, 0.f);
                    xa[2 * p] = v.x; xa[2 * p + 1] = v.y;
                }
            } else {
#pragma unroll
                for (int p = 0; p < 7; p++) {
                    bool ok = rok && ((unsigned)(gc0 + 2 * p) < (unsigned)IW);
                    float2 v = ok ? xrow2[p] : make_float2(0.f, 0.f);
                    xa[2 * p] = v.x; xa[2 * p + 1] = v.y;
                }
            }
            float2 o[7];
#pragma unroll
            for (int k = 0; k < 7; k++) {
                o[k] = make_float2(
                    UP_E(xa[k],xa[k+1],xa[k+2],xa[k+3],xa[k+4],xa[k+5]),
                    UP_O(xa[k],xa[k+1],xa[k+2],xa[k+3],xa[k+4],xa[k+5]));
            }
            float* trow = t + r * TP + 12 * s;
            *reinterpret_cast<float4*>(trow)      = make_float4(o[0].x,o[0].y,o[1].x,o[1].y);
            *reinterpret_cast<float4*>(trow + 4)  = make_float4(o[2].x,o[2].y,o[3].x,o[3].y);
            *reinterpret_cast<float4*>(trow + 8)  = make_float4(o[4].x,o[4].y,o[5].x,o[5].y);
            *reinterpret_cast<float2*>(trow + 12) = o[6];
        }
    }
    __syncthreads();

    // ---- Stage B: per-column up-V + lrelu + down-V, f32x2 over (ze,zo).
    // 74 cols x 2 row-segments (32 outputs each, 37 steps). Column j is
    // thread-private, so seg0 (rows 0..31) stores its outputs IN PLACE into
    // t rows 0..31 (each slot k-5 is dead before the step-k write; seg1 never
    // reads rows <32). seg1 stores into w1. Guards: acc_i update at step k
    // useful iff 5 <= k+i <= 36 (compile-time).
    if (tid < 148) {
        const int seg = (tid >= 74) ? 1 : 0;
        const int j   = tid - 74 * seg;
        const float* tc = t + (seg << 5) * TP + j;
        float* wc = (seg ? w1 : t) + j;            // write base, stride TP
        const float2 P0 = make_float2(g1, g0), P1 = make_float2(g3, g2),
                     P2 = make_float2(g5, g4), P3 = make_float2(g4, g5),
                     P4 = make_float2(g2, g3), P5 = make_float2(g0, g1);
        const float2 ED0 = make_float2(e1, e0), ED1 = make_float2(e3, e2),
                     ED2 = make_float2(e5, e4), ED3 = make_float2(e4, e5),
                     ED4 = make_float2(e2, e3), ED5 = make_float2(e0, e1);
        float2 wb[6];
#pragma unroll
        for (int i = 0; i < 6; i++) {
            float v = tc[i * TP];
            wb[i] = make_float2(v, v);
        }
        float2 acc0 = make_float2(0.f, 0.f), acc1 = acc0, acc2 = acc0,
               acc3 = acc0, acc4 = acc0;
#pragma unroll
        for (int k = 0; k < 37; k++) {
            float2 zz = fmul2(P0, wb[k % 6]);
            zz = ffma2(P1, wb[(k + 1) % 6], zz);
            zz = ffma2(P2, wb[(k + 2) % 6], zz);
            zz = ffma2(P3, wb[(k + 3) % 6], zz);
            zz = ffma2(P4, wb[(k + 4) % 6], zz);
            zz = ffma2(P5, wb[(k + 5) % 6], zz);
            zz.x = fmaxf(zz.x, 0.01f * zz.x);      // lrelu on both phases
            zz.y = fmaxf(zz.y, 0.01f * zz.y);
            if (k >= 5)            acc0 = ffma2(ED0, zz, acc0);
            if (k >= 4 && k <= 35) acc1 = ffma2(ED1, zz, acc1);
            if (k >= 3 && k <= 34) acc2 = ffma2(ED2, zz, acc2);
            if (k >= 2 && k <= 33) acc3 = ffma2(ED3, zz, acc3);
            if (k >= 1 && k <= 32) acc4 = ffma2(ED4, zz, acc4);
            if (k >= 5) wc[(k - 5) * TP] = acc0.x + acc0.y;
            acc0 = acc1; acc1 = acc2; acc2 = acc3; acc3 = acc4;
            if (k <= 31) acc4 = fmul2(ED5, zz);    // fresh tail accumulator
            if (k <= 35) {                         // slide: load row k+6
                float v = tc[(k + 6) * TP];
                wb[k % 6] = make_float2(v, v);
            }
        }
    }
    __syncthreads();

    // ---- Stage C: horizontal down + store. 64 rows x 8 segs = 512 jobs,
    // 2 per thread. w row m lives at t[m] (m<32) or w1[m-32] (m>=32).
    {
        float* ob = out + (size_t)ch * OW * OW;
#pragma unroll 1
        for (int it = 0; it < 2; it++) {
            const int job = tid + it * NTHREADS;
            const int m = job >> 3, s = job & 7;
            const float* wrow = (m < 32) ? (t + m * TP) : (w1 + (m - 32) * TP);
            const float4* wr = reinterpret_cast<const float4*>(wrow) + 2 * s;
            float4 q0 = wr[0], q1 = wr[1], q2 = wr[2], q3 = wr[3], q4 = wr[4];
            float v0=q0.x,v1=q0.y,v2=q0.z,v3=q0.w,
                  v4=q1.x,v5=q1.y,v6=q1.z,v7=q1.w,
                  v8=q2.x,v9=q2.y,v10=q2.z,v11=q2.w,
                  v12=q3.x,v13=q3.y,v14=q3.z,v15=q3.w,
                  v16=q4.x,v17=q4.y;
            float o0 = DN(v0,v1,v2,v3,v4,v5,v6,v7,v8,v9,v10,v11);
            float o1 = DN(v2,v3,v4,v5,v6,v7,v8,v9,v10,v11,v12,v13);
            float o2 = DN(v4,v5,v6,v7,v8,v9,v10,v11,v12,v13,v14,v15);
            float o3 = DN(v6,v7,v8,v9,v10,v11,v12,v13,v14,v15,v16,v17);
            float* od = ob + (size_t)(m0 + m) * OW + n0 + 4 * s;
            *reinterpret_cast<float4*>(od) = make_float4(o0, o1, o2, o3);
        }
    }
}

extern "C" void kernel_launch(void* const* d_in, const int* in_sizes, int n_in,
                              void* d_out, int out_size) {
    const float* x   = (const float*)d_in[0];
    const float* fup = (const float*)d_in[1];
    const float* fdn = (const float*)d_in[2];
    float* out = (float*)d_out;
    dim3 grid(8, 1024);
    flrelu_fused_kernel<<<grid, NTHREADS>>>(x, fup, fdn, out);
}